// round 8
// baseline (speedup 1.0000x reference)
#include <cuda_runtime.h>

#define DIM     33
#define DIM2    (DIM*DIM)            // 1089
#define CELLS   (DIM*DIM*DIM)        // 35937
#define PLANE   (1080*1920)          // 2073600 pixels per channel plane
#define NIMG    16
#define GPI     (PLANE/4)            // 518400 groups of 4 pixels per image

// One 32B-aligned entry per cell (b,g,r) holds ALL 8 corners x 3 channels at
// 10-bit fixed point: word k (k = cb*4+cg*2+cr) = R | G<<10 | B<<20.
// A pixel reads its entry with ONE 256-bit load (ld.global.nc.v8.b32).
struct __align__(32) Cell2 { uint4 lo, hi; };
__device__ Cell2 g_cell2[CELLS];     // 1.15 MB, L2-resident

__global__ void repack_kernel(const float* __restrict__ lut) {
    int i = blockIdx.x * blockDim.x + threadIdx.x;
    if (i >= CELLS) return;
    int b = i / DIM2;
    int rem = i - b * DIM2;
    int g = rem / DIM;
    int r = rem - g * DIM;
    int rr[2] = { r, min(r + 1, DIM - 1) };
    int gg[2] = { g, min(g + 1, DIM - 1) };
    int bb[2] = { b, min(b + 1, DIM - 1) };

    unsigned w[8];
    #pragma unroll
    for (int cb = 0; cb < 2; cb++)
      #pragma unroll
      for (int cg = 0; cg < 2; cg++)
        #pragma unroll
        for (int cr = 0; cr < 2; cr++) {
            int idx = bb[cb] * DIM2 + gg[cg] * DIM + rr[cr];
            unsigned R = (unsigned)rintf(lut[idx]             * 1023.0f);
            unsigned G = (unsigned)rintf(lut[idx + CELLS]     * 1023.0f);
            unsigned B = (unsigned)rintf(lut[idx + 2 * CELLS] * 1023.0f);
            w[cb * 4 + cg * 2 + cr] = R | (G << 10) | (B << 20);
        }
    Cell2 c;
    c.lo = make_uint4(w[0], w[1], w[2], w[3]);
    c.hi = make_uint4(w[4], w[5], w[6], w[7]);
    g_cell2[i] = c;
}

#define MAGIC 0x4B000000u            // as_float(MAGIC | q) = 2^23 + q, exact
#define BIGC  8388608.0f             // 2^23

// Trilinear lerp over 8 biased corners f[k] = 2^23 + q_k.
// Diffs (f1-f0 = q1-q0) and addends (f0 - 2^23 = q0) are EXACT.
__device__ __forceinline__ float trilerp(const float* f,
                                         float rd, float gd, float bd) {
    float c00 = fmaf(rd, f[1] - f[0], f[0] - BIGC);
    float c10 = fmaf(rd, f[3] - f[2], f[2] - BIGC);
    float c01 = fmaf(rd, f[5] - f[4], f[4] - BIGC);
    float c11 = fmaf(rd, f[7] - f[6], f[6] - BIGC);
    float c0  = fmaf(gd, c10 - c00, c00);
    float c1  = fmaf(gd, c11 - c01, c01);
    return fmaf(bd, c1 - c0, c0);
}

__global__ __launch_bounds__(256) void lut3d_kernel(
    const float* __restrict__ x, float* __restrict__ out)
{
    int tid = blockIdx.x * blockDim.x + threadIdx.x;   // one thread = 4 pixels
    int n  = tid / GPI;
    int p4 = (tid - n * GPI) * 4;

    size_t base = (size_t)n * 3 * PLANE + p4;
    // streaming loads: evict-first, don't pollute the LUT-resident cache
    float4 rv = __ldcs((const float4*)(x + base));
    float4 gv = __ldcs((const float4*)(x + base + PLANE));
    float4 bv = __ldcs((const float4*)(x + base + 2 * PLANE));

    const float inv = 32.0f / 1.000001f;   // 1/binsize
    float rA[4] = { rv.x, rv.y, rv.z, rv.w };
    float gA[4] = { gv.x, gv.y, gv.z, gv.w };
    float bA[4] = { bv.x, bv.y, bv.z, bv.w };

    int   i00[4];
    float rd[4], gd[4], bd[4];
    #pragma unroll
    for (int s = 0; s < 4; s++) {
        float tr = rA[s] * inv, tg = gA[s] * inv, tb = bA[s] * inv;
        int ir = (int)tr, ig = (int)tg, ib = (int)tb;   // floor (x >= 0)
        rd[s] = tr - (float)ir;
        gd[s] = tg - (float)ig;
        bd[s] = tb - (float)ib;
        ir = min(ir, DIM - 2);      // x >= 0 -> lower clamp unnecessary
        ig = min(ig, DIM - 2);
        ib = min(ib, DIM - 2);
        i00[s] = ib * DIM2 + ig * DIM + ir;
    }

    // Batch all 4 divergent 256-bit gathers (MLP=4) before any math.
    unsigned w[4][8];
    #pragma unroll
    for (int s = 0; s < 4; s++) {
        const void* p = (const void*)&g_cell2[i00[s]];
        asm volatile("ld.global.nc.v8.b32 {%0,%1,%2,%3,%4,%5,%6,%7}, [%8];"
                     : "=r"(w[s][0]), "=r"(w[s][1]), "=r"(w[s][2]), "=r"(w[s][3]),
                       "=r"(w[s][4]), "=r"(w[s][5]), "=r"(w[s][6]), "=r"(w[s][7])
                     : "l"(p));
    }

    const float sc = 1.0f / 1023.0f;
    float oR[4], oG[4], oB[4];
    #pragma unroll
    for (int s = 0; s < 4; s++) {
        float fR[8], fG[8], fB[8];
        #pragma unroll
        for (int k = 0; k < 8; k++) {
            unsigned ww = w[s][k];
            fR[k] = __uint_as_float(( ww        & 1023u) | MAGIC);  // LOP3
            fG[k] = __uint_as_float(((ww >> 10) & 1023u) | MAGIC);  // SHF+LOP3
            fB[k] = __uint_as_float( (ww >> 20)          | MAGIC);  // SHF+LOP
        }
        oR[s] = trilerp(fR, rd[s], gd[s], bd[s]) * sc;
        oG[s] = trilerp(fG, rd[s], gd[s], bd[s]) * sc;
        oB[s] = trilerp(fB, rd[s], gd[s], bd[s]) * sc;
    }

    __stcs((float4*)(out + base),             make_float4(oR[0], oR[1], oR[2], oR[3]));
    __stcs((float4*)(out + base + PLANE),     make_float4(oG[0], oG[1], oG[2], oG[3]));
    __stcs((float4*)(out + base + 2 * PLANE), make_float4(oB[0], oB[1], oB[2], oB[3]));
}

extern "C" void kernel_launch(void* const* d_in, const int* in_sizes, int n_in,
                              void* d_out, int out_size) {
    const float* lut = (const float*)d_in[0];   // (3, 33, 33, 33) fp32
    const float* x   = (const float*)d_in[1];   // (16, 3, 1080, 1920) fp32
    float* out = (float*)d_out;                 // (16, 3, 1080, 1920) fp32

    repack_kernel<<<(CELLS + 255) / 256, 256>>>(lut);

    int total_groups = NIMG * GPI;              // 8,294,400 threads
    lut3d_kernel<<<total_groups / 256, 256>>>(x, out);
}

// round 9
// speedup vs baseline: 1.4280x; 1.4280x over previous
#include <cuda_runtime.h>

#define DIM     33
#define DIM2    (DIM*DIM)            // 1089
#define CELLS   (DIM*DIM*DIM)        // 35937
#define PLANE   (1080*1920)          // 2073600 pixels per channel plane
#define NIMG    16
#define GPI2    (PLANE/2)            // 1036800 pixel-pairs per image

// One 32B-aligned entry per cell (b,g,r) holds ALL 8 corners x 3 channels at
// 10-bit fixed point: word k (k = cb*4+cg*2+cr) = R | G<<10 | B<<20.
// A pixel reads its entry with ONE 256-bit load (ld.global.nc.v8.b32).
struct __align__(32) Cell2 { uint4 lo, hi; };
__device__ Cell2 g_cell2[CELLS];     // 1.15 MB, L2-resident

__global__ void repack_kernel(const float* __restrict__ lut) {
    int i = blockIdx.x * blockDim.x + threadIdx.x;
    if (i >= CELLS) return;
    int b = i / DIM2;
    int rem = i - b * DIM2;
    int g = rem / DIM;
    int r = rem - g * DIM;
    int rr[2] = { r, min(r + 1, DIM - 1) };
    int gg[2] = { g, min(g + 1, DIM - 1) };
    int bb[2] = { b, min(b + 1, DIM - 1) };

    unsigned w[8];
    #pragma unroll
    for (int cb = 0; cb < 2; cb++)
      #pragma unroll
      for (int cg = 0; cg < 2; cg++)
        #pragma unroll
        for (int cr = 0; cr < 2; cr++) {
            int idx = bb[cb] * DIM2 + gg[cg] * DIM + rr[cr];
            unsigned R = (unsigned)rintf(lut[idx]             * 1023.0f);
            unsigned G = (unsigned)rintf(lut[idx + CELLS]     * 1023.0f);
            unsigned B = (unsigned)rintf(lut[idx + 2 * CELLS] * 1023.0f);
            w[cb * 4 + cg * 2 + cr] = R | (G << 10) | (B << 20);
        }
    Cell2 c;
    c.lo = make_uint4(w[0], w[1], w[2], w[3]);
    c.hi = make_uint4(w[4], w[5], w[6], w[7]);
    g_cell2[i] = c;
}

struct F3 { float x, y, z; };

#define MAGIC 0x4B000000u            // as_float(MAGIC | q) = 2^23 + q, exact
#define BIGC  8388608.0f             // 2^23

// Trilinear lerp over 8 biased corners f[k] = 2^23 + q_k.
// Diffs (f1-f0 = q1-q0) and addends (f0 - 2^23 = q0) are EXACT.
__device__ __forceinline__ float trilerp(const float* f,
                                         float rd, float gd, float bd) {
    float c00 = fmaf(rd, f[1] - f[0], f[0] - BIGC);
    float c10 = fmaf(rd, f[3] - f[2], f[2] - BIGC);
    float c01 = fmaf(rd, f[5] - f[4], f[4] - BIGC);
    float c11 = fmaf(rd, f[7] - f[6], f[6] - BIGC);
    float c0  = fmaf(gd, c10 - c00, c00);
    float c1  = fmaf(gd, c11 - c01, c01);
    return fmaf(bd, c1 - c0, c0);
}

__device__ __forceinline__ F3 sample_lut(float r, float g, float b) {
    const float inv = 32.0f / 1.000001f;   // 1/binsize
    float tr = r * inv, tg = g * inv, tb = b * inv;

    int ir = (int)tr, ig = (int)tg, ib = (int)tb;    // floor (x >= 0)
    float rd = tr - (float)ir;
    float gd = tg - (float)ig;
    float bd = tb - (float)ib;
    ir = min(ir, DIM - 2);      // x >= 0 -> no lower clamp needed
    ig = min(ig, DIM - 2);
    ib = min(ib, DIM - 2);

    int i00 = ib * DIM2 + ig * DIM + ir;

    // Single 256-bit non-coherent load of the whole cell (sm_10x).
    unsigned w[8];
    {
        const void* p = (const void*)&g_cell2[i00];
        asm volatile("ld.global.nc.v8.b32 {%0,%1,%2,%3,%4,%5,%6,%7}, [%8];"
                     : "=r"(w[0]), "=r"(w[1]), "=r"(w[2]), "=r"(w[3]),
                       "=r"(w[4]), "=r"(w[5]), "=r"(w[6]), "=r"(w[7])
                     : "l"(p));
    }

    float fR[8], fG[8], fB[8];
    #pragma unroll
    for (int k = 0; k < 8; k++) {
        fR[k] = __uint_as_float(( w[k]        & 1023u) | MAGIC);  // LOP3
        fG[k] = __uint_as_float(((w[k] >> 10) & 1023u) | MAGIC);  // SHF+LOP3
        fB[k] = __uint_as_float( (w[k] >> 20)          | MAGIC);  // SHF+LOP
    }

    const float s = 1.0f / 1023.0f;
    F3 o;
    o.x = trilerp(fR, rd, gd, bd) * s;
    o.y = trilerp(fG, rd, gd, bd) * s;
    o.z = trilerp(fB, rd, gd, bd) * s;
    return o;
}

__global__ __launch_bounds__(256) void lut3d_kernel(
    const float* __restrict__ x, float* __restrict__ out)
{
    int tid = blockIdx.x * blockDim.x + threadIdx.x;   // one thread = 2 pixels
    int n  = tid / GPI2;
    int p2 = (tid - n * GPI2) * 2;

    size_t base = (size_t)n * 3 * PLANE + p2;
    // streaming loads: evict-first, don't pollute the LUT-resident cache
    float2 rv = __ldcs((const float2*)(x + base));
    float2 gv = __ldcs((const float2*)(x + base + PLANE));
    float2 bv = __ldcs((const float2*)(x + base + 2 * PLANE));

    F3 o0 = sample_lut(rv.x, gv.x, bv.x);
    F3 o1 = sample_lut(rv.y, gv.y, bv.y);

    __stcs((float2*)(out + base),             make_float2(o0.x, o1.x));
    __stcs((float2*)(out + base + PLANE),     make_float2(o0.y, o1.y));
    __stcs((float2*)(out + base + 2 * PLANE), make_float2(o0.z, o1.z));
}

extern "C" void kernel_launch(void* const* d_in, const int* in_sizes, int n_in,
                              void* d_out, int out_size) {
    const float* lut = (const float*)d_in[0];   // (3, 33, 33, 33) fp32
    const float* x   = (const float*)d_in[1];   // (16, 3, 1080, 1920) fp32
    float* out = (float*)d_out;                 // (16, 3, 1080, 1920) fp32

    repack_kernel<<<(CELLS + 255) / 256, 256>>>(lut);

    int total_threads = NIMG * GPI2;            // 16,588,800 threads
    lut3d_kernel<<<total_threads / 256, 256>>>(x, out);
}

// round 10
// speedup vs baseline: 1.6068x; 1.1252x over previous
#include <cuda_runtime.h>

#define DIM     33
#define DIM2    (DIM*DIM)            // 1089
#define CELLS   (DIM*DIM*DIM)        // 35937
#define PLANE   (1080u*1920u)        // 2073600 pixels per channel plane
#define NIMG    16
#define GPI     (PLANE/4u)           // 518400 groups of 4 pixels per image

// One 32B-aligned entry per cell (b,g,r) holds ALL 8 corners x 3 channels at
// 10-bit fixed point: word k (k = cb*4+cg*2+cr) = R | G<<10 | B<<20.
// A pixel reads its entry with ONE 256-bit load (ld.global.nc.v8.b32).
struct __align__(32) Cell2 { uint4 lo, hi; };
__device__ Cell2 g_cell2[CELLS];     // 1.15 MB, L2-resident

__global__ void repack_kernel(const float* __restrict__ lut) {
    int i = blockIdx.x * blockDim.x + threadIdx.x;
    if (i >= CELLS) return;
    int b = i / DIM2;
    int rem = i - b * DIM2;
    int g = rem / DIM;
    int r = rem - g * DIM;
    int rr[2] = { r, min(r + 1, DIM - 1) };
    int gg[2] = { g, min(g + 1, DIM - 1) };
    int bb[2] = { b, min(b + 1, DIM - 1) };

    unsigned w[8];
    #pragma unroll
    for (int cb = 0; cb < 2; cb++)
      #pragma unroll
      for (int cg = 0; cg < 2; cg++)
        #pragma unroll
        for (int cr = 0; cr < 2; cr++) {
            int idx = bb[cb] * DIM2 + gg[cg] * DIM + rr[cr];
            unsigned R = (unsigned)rintf(lut[idx]             * 1023.0f);
            unsigned G = (unsigned)rintf(lut[idx + CELLS]     * 1023.0f);
            unsigned B = (unsigned)rintf(lut[idx + 2 * CELLS] * 1023.0f);
            w[cb * 4 + cg * 2 + cr] = R | (G << 10) | (B << 20);
        }
    Cell2 c;
    c.lo = make_uint4(w[0], w[1], w[2], w[3]);
    c.hi = make_uint4(w[4], w[5], w[6], w[7]);
    g_cell2[i] = c;
}

struct F3 { float x, y, z; };

#define MAGIC 0x4B000000u            // as_float(MAGIC | q) = 2^23 + q, exact
#define BIGC  8388608.0f             // 2^23

// Trilinear lerp over 8 biased corners f[k] = 2^23 + q_k.
// Diffs (f1-f0 = q1-q0) and addends (f0 - 2^23 = q0) are EXACT.
__device__ __forceinline__ float trilerp(const float* f,
                                         float rd, float gd, float bd) {
    float c00 = fmaf(rd, f[1] - f[0], f[0] - BIGC);
    float c10 = fmaf(rd, f[3] - f[2], f[2] - BIGC);
    float c01 = fmaf(rd, f[5] - f[4], f[4] - BIGC);
    float c11 = fmaf(rd, f[7] - f[6], f[6] - BIGC);
    float c0  = fmaf(gd, c10 - c00, c00);
    float c1  = fmaf(gd, c11 - c01, c01);
    return fmaf(bd, c1 - c0, c0);
}

__device__ __forceinline__ F3 sample_lut(float r, float g, float b) {
    const float inv = 32.0f / 1.000001f;   // 1/binsize
    float tr = r * inv, tg = g * inv, tb = b * inv;

    int ir = (int)tr, ig = (int)tg, ib = (int)tb;    // floor (x >= 0)
    float rd = tr - (float)ir;
    float gd = tg - (float)ig;
    float bd = tb - (float)ib;
    ir = min(ir, DIM - 2);      // x >= 0 -> no lower clamp needed
    ig = min(ig, DIM - 2);
    ib = min(ib, DIM - 2);

    int i00 = ib * DIM2 + ig * DIM + ir;

    // Single 256-bit non-coherent load of the whole cell (sm_10x).
    unsigned w[8];
    {
        const void* p = (const void*)&g_cell2[i00];
        asm volatile("ld.global.nc.v8.b32 {%0,%1,%2,%3,%4,%5,%6,%7}, [%8];"
                     : "=r"(w[0]), "=r"(w[1]), "=r"(w[2]), "=r"(w[3]),
                       "=r"(w[4]), "=r"(w[5]), "=r"(w[6]), "=r"(w[7])
                     : "l"(p));
    }

    float fR[8], fG[8], fB[8];
    #pragma unroll
    for (int k = 0; k < 8; k++) {
        fR[k] = __uint_as_float(( w[k]        & 1023u) | MAGIC);  // LOP3
        fG[k] = __uint_as_float(((w[k] >> 10) & 1023u) | MAGIC);  // SHF+LOP3
        fB[k] = __uint_as_float( (w[k] >> 20)          | MAGIC);  // SHF+LOP
    }

    const float s = 1.0f / 1023.0f;
    F3 o;
    o.x = trilerp(fR, rd, gd, bd) * s;
    o.y = trilerp(fG, rd, gd, bd) * s;
    o.z = trilerp(fB, rd, gd, bd) * s;
    return o;
}

__global__ __launch_bounds__(256) void lut3d_kernel(
    const float* __restrict__ x, float* __restrict__ out)
{
    unsigned tid = blockIdx.x * blockDim.x + threadIdx.x; // one thread = 4 px
    unsigned n  = tid / GPI;
    unsigned p4 = (tid - n * GPI) * 4u;

    // 32-bit offsets: total elements 99.5M < 2^31 -> no 64-bit index math
    unsigned base = n * 3u * PLANE + p4;
    const float4* xr = (const float4*)(x + base);
    const float4* xg = (const float4*)(x + base + PLANE);
    const float4* xb = (const float4*)(x + base + 2u * PLANE);
    float4 rv = __ldcs(xr);
    float4 gv = __ldcs(xg);
    float4 bv = __ldcs(xb);

    F3 o0 = sample_lut(rv.x, gv.x, bv.x);
    F3 o1 = sample_lut(rv.y, gv.y, bv.y);
    F3 o2 = sample_lut(rv.z, gv.z, bv.z);
    F3 o3 = sample_lut(rv.w, gv.w, bv.w);

    __stcs((float4*)(out + base),              make_float4(o0.x, o1.x, o2.x, o3.x));
    __stcs((float4*)(out + base + PLANE),      make_float4(o0.y, o1.y, o2.y, o3.y));
    __stcs((float4*)(out + base + 2u * PLANE), make_float4(o0.z, o1.z, o2.z, o3.z));
}

extern "C" void kernel_launch(void* const* d_in, const int* in_sizes, int n_in,
                              void* d_out, int out_size) {
    const float* lut = (const float*)d_in[0];   // (3, 33, 33, 33) fp32
    const float* x   = (const float*)d_in[1];   // (16, 3, 1080, 1920) fp32
    float* out = (float*)d_out;                 // (16, 3, 1080, 1920) fp32

    repack_kernel<<<(CELLS + 255) / 256, 256>>>(lut);

    unsigned total_groups = NIMG * GPI;         // 8,294,400 threads
    lut3d_kernel<<<total_groups / 256, 256>>>(x, out);
}